// round 1
// baseline (speedup 1.0000x reference)
#include <cuda_runtime.h>
#include <cstddef>

#define G_CELLS 8000
#define T_STEPS 730
#define PF 5            // 730 = 5 * 146, exact
#define NEARZERO_F 1e-5f

__global__ __launch_bounds__(64) void hbv_kernel(
    const float* __restrict__ xphy,    // [730, 8000, 3] (P, T, PET)
    const float* __restrict__ params,  // [730, 8000, 14]
    float* __restrict__ out)           // [730, 8000]
{
    const int g = blockIdx.x * blockDim.x + threadIdx.x;
    if (g >= G_CELLS) return;

    // Parameter bounds (lo, hi) in order:
    // BETA, FC, K0, K1, K2, LP, PERCmax, UZL, TT, CFMAX, CFR, CWH, BETAET, C
    const float lo[14] = {1.0f, 50.0f, 0.05f, 0.01f, 0.001f, 0.2f, 0.0f,
                          0.0f, -2.5f, 0.5f, 0.0f, 0.0f, 0.3f, 0.0f};
    const float hi[14] = {6.0f, 1000.0f, 0.9f, 0.5f, 0.2f, 1.0f, 10.0f,
                          100.0f, 2.5f, 10.0f, 0.1f, 0.2f, 5.0f, 1.0f};

    // Only the LAST timestep's parameters are used.
    const float* pr = params + ((size_t)(T_STEPS - 1) * G_CELLS + (size_t)g) * 14;
    float phy[14];
#pragma unroll
    for (int i = 0; i < 14; i++) {
        float s = 1.0f / (1.0f + __expf(-pr[i]));   // sigmoid
        phy[i] = lo[i] + s * (hi[i] - lo[i]);
    }
    const float BETA = phy[0],  FC = phy[1],     K0 = phy[2],  K1 = phy[3];
    const float K2 = phy[4],    LP = phy[5],     PERCmax = phy[6];
    const float UZL = phy[7],   TT = phy[8],     CFMAX = phy[9];
    const float CFR = phy[10],  CWH = phy[11],   BETAET = phy[12], C = phy[13];

    const float invFC   = 1.0f / FC;
    const float invLPFC = 1.0f / (LP * FC);
    const float CFRCF   = CFR * CFMAX;

    float SP = 0.001f, MW = 0.001f, SM = 0.001f, SUZ = 0.001f, SLZ = 0.001f;

    // Register ring buffer: prefetch PF steps ahead so DRAM latency (~600cyc)
    // hides behind ~PF * chain (~850cyc) of compute.
    float pP[PF], pT[PF], pE[PF];
#pragma unroll
    for (int i = 0; i < PF; i++) {
        const float* xp = xphy + ((size_t)i * G_CELLS + (size_t)g) * 3;
        pP[i] = xp[0]; pT[i] = xp[1]; pE[i] = xp[2];
    }

    for (int t0 = 0; t0 < T_STEPS; t0 += PF) {
#pragma unroll
        for (int i = 0; i < PF; i++) {
            const int t = t0 + i;
            const float Pt = pP[i], Tt = pT[i], PETt = pE[i];

            // Prefetch step t+PF into this slot (independent of the chain).
            const int tn = t + PF;
            if (tn < T_STEPS) {
                const float* xp = xphy + ((size_t)tn * G_CELLS + (size_t)g) * 3;
                pP[i] = xp[0]; pT[i] = xp[1]; pE[i] = xp[2];
            }

            // --- snow routine ---
            const float is_rain = (Tt >= TT) ? 1.0f : 0.0f;
            const float RAIN = Pt * is_rain;
            const float SNOW = Pt - RAIN;
            SP += SNOW;
            const float melt = fminf(fmaxf(CFMAX * (Tt - TT), 0.0f), SP);
            MW += melt;  SP -= melt;
            const float refreeze = fminf(fmaxf(CFRCF * (TT - Tt), 0.0f), MW);
            SP += refreeze;  MW -= refreeze;
            const float tosoil = fmaxf(MW - CWH * SP, 0.0f);
            MW -= tosoil;

            // --- soil moisture ---
            // base > 0 always, so clip(.,0,1) == fminf(.,1)
            const float sw = fminf(__powf(SM * invFC, BETA), 1.0f);
            const float recharge = (RAIN + tosoil) * sw;
            SM += RAIN + tosoil - recharge;
            const float excess = fmaxf(SM - FC, 0.0f);
            SM -= excess;
            const float ef = fminf(__powf(SM * invLPFC, BETAET), 1.0f);
            const float ETact = fminf(SM, PETt * ef);
            SM = fmaxf(SM - ETact, NEARZERO_F);
            const float capillary =
                fminf(SLZ, C * SLZ * (1.0f - fminf(SM * invFC, 1.0f)));
            SM  = fmaxf(SM + capillary, NEARZERO_F);
            SLZ = fmaxf(SLZ - capillary, NEARZERO_F);

            // --- response routine ---
            SUZ += recharge + excess;
            const float PERC = fminf(SUZ, PERCmax);
            SUZ -= PERC;
            const float Q0 = K0 * fmaxf(SUZ - UZL, 0.0f);
            SUZ -= Q0;
            const float Q1 = K1 * SUZ;
            SUZ -= Q1;
            SLZ += PERC;
            const float Q2 = K2 * SLZ;
            SLZ -= Q2;

            out[(size_t)t * G_CELLS + (size_t)g] = Q0 + Q1 + Q2;
        }
    }
}

extern "C" void kernel_launch(void* const* d_in, const int* in_sizes, int n_in,
                              void* d_out, int out_size) {
    const float* xphy   = (const float*)d_in[0];   // 730*8000*3
    const float* params = (const float*)d_in[1];   // 730*8000*14
    float* out = (float*)d_out;                    // 730*8000

    const int threads = 64;
    const int blocks  = (G_CELLS + threads - 1) / threads;  // 125
    hbv_kernel<<<blocks, threads>>>(xphy, params, out);
}

// round 2
// speedup vs baseline: 1.0936x; 1.0936x over previous
#include <cuda_runtime.h>
#include <cstddef>

#define G_CELLS 8000
#define T_STEPS 730
#define PF 5            // 730 = 5 * 146, exact
#define NEARZERO_F 1e-5f

__device__ __forceinline__ float ex2f_(float x) {
    float r; asm("ex2.approx.f32 %0, %1;" : "=f"(r) : "f"(x)); return r;
}
__device__ __forceinline__ float lg2f_(float x) {
    float r; asm("lg2.approx.f32 %0, %1;" : "=f"(r) : "f"(x)); return r;
}

__global__ __launch_bounds__(64) void hbv_kernel(
    const float* __restrict__ xphy,    // [730, 8000, 3] (P, T, PET)
    const float* __restrict__ params,  // [730, 8000, 14]
    float* __restrict__ out)           // [730, 8000]
{
    const int g = blockIdx.x * blockDim.x + threadIdx.x;
    if (g >= G_CELLS) return;

    // BETA, FC, K0, K1, K2, LP, PERCmax, UZL, TT, CFMAX, CFR, CWH, BETAET, C
    const float lo[14] = {1.0f, 50.0f, 0.05f, 0.01f, 0.001f, 0.2f, 0.0f,
                          0.0f, -2.5f, 0.5f, 0.0f, 0.0f, 0.3f, 0.0f};
    const float hi[14] = {6.0f, 1000.0f, 0.9f, 0.5f, 0.2f, 1.0f, 10.0f,
                          100.0f, 2.5f, 10.0f, 0.1f, 0.2f, 5.0f, 1.0f};

    const float* pr = params + ((size_t)(T_STEPS - 1) * G_CELLS + (size_t)g) * 14;
    float phy[14];
#pragma unroll
    for (int i = 0; i < 14; i++) {
        const float s = 1.0f / (1.0f + __expf(-pr[i]));
        phy[i] = fmaf(s, hi[i] - lo[i], lo[i]);
    }
    const float BETA = phy[0],  FC = phy[1],     K0 = phy[2],  K1 = phy[3];
    const float K2 = phy[4],    LP = phy[5],     PERCmax = phy[6];
    const float UZL = phy[7],   TT = phy[8],     CFMAX = phy[9];
    const float CFR = phy[10],  CWH = phy[11],   BETAET = phy[12], C = phy[13];

    const float invFC   = 1.0f / FC;
    const float invLPFC = 1.0f / (LP * FC);
    const float CFRCF   = CFR * CFMAX;
    // pow constant folds: (x*s)^b = ex2( b*lg2(x) + b*lg2(s) )
    const float clgA = BETA   * lg2f_(invFC);
    const float clgB = BETAET * lg2f_(invLPFC);
    const float oneK0 = 1.0f - K0;
    const float K0UZL = K0 * UZL;
    const float oneK1 = 1.0f - K1;
    const float oneK2 = 1.0f - K2;

    float SP = 0.001f, MW = 0.001f, SM = 0.001f, SUZ = 0.001f, SLZ = 0.001f;
    float CSLZ  = C * SLZ;          // precomputed off-path per step
    float CSLZF = CSLZ * invFC;

    // Register ring buffer, prefetch depth PF.
    float pP[PF], pT[PF], pE[PF];
#pragma unroll
    for (int i = 0; i < PF; i++) {
        const float* xp = xphy + ((size_t)i * G_CELLS + (size_t)g) * 3;
        pP[i] = xp[0]; pT[i] = xp[1]; pE[i] = xp[2];
    }

    float* op = out + g;

    auto step = [&](float Pt, float Tt, float PETt, int t) {
        // --- snow routine (off the SM critical path) ---
        const float dT   = Tt - TT;
        const float RAIN = (dT >= 0.0f) ? Pt : 0.0f;
        const float SNOW = Pt - RAIN;
        float SP1 = SP + SNOW;
        const float melt = fminf(fmaxf(CFMAX * dT, 0.0f), SP1);
        float MW1 = MW + melt;
        SP1 -= melt;
        const float refreeze = fminf(fmaxf(-CFRCF * dT, 0.0f), MW1);
        SP = SP1 + refreeze;
        MW1 -= refreeze;
        const float tosoil = fmaxf(fmaf(-CWH, SP, MW1), 0.0f);
        MW = MW1 - tosoil;
        const float inflow = RAIN + tosoil;

        // --- SM critical path ---
        const float e1 = ex2f_(fmaf(BETA, lg2f_(SM), clgA));      // (SM/FC)^BETA
        const float t1 = SM + inflow;                              // off-path
        const float recharge = fminf(inflow * e1, inflow);         // off-path (SUZ)
        // SM1 = SM + inflow - inflow*min(e1,1) = max(fma(-inflow,e1,t1), SM)
        const float SM1 = fmaxf(fmaf(-inflow, e1, t1), SM);
        const float excess = fmaxf(SM1 - FC, 0.0f);                // off-path (SUZ)
        const float SM2 = fminf(SM1, FC);
        const float e2 = ex2f_(fmaf(BETAET, lg2f_(SM2), clgB));   // (SM2/(LP*FC))^BETAET
        const float floor3 = fmaxf(SM2 - PETt, NEARZERO_F);        // off-path
        // SM3 = max(SM2 - min(SM2, PET*min(e2,1)), eps)
        const float SM3 = fmaxf(fmaf(-PETt, e2, SM2), floor3);
        // capillary = min(SLZ, C*SLZ*(1 - min(SM3/FC,1)))
        const float cap = fmaxf(fminf(fmaf(-CSLZF, SM3, CSLZ), SLZ), 0.0f);
        SM = SM3 + cap;   // max(.,eps) redundant: cap>=0, SM3>=eps

        // --- response routine (off-path chains) ---
        const float SUZ1 = SUZ + (recharge + excess);
        const float PERC = fminf(SUZ1, PERCmax);
        const float SUZ2 = SUZ1 - PERC;
        // SUZ3 = SUZ2 - K0*max(SUZ2-UZL,0) = min(SUZ2, (1-K0)*SUZ2 + K0*UZL)
        const float SUZ3 = fminf(SUZ2, fmaf(oneK0, SUZ2, K0UZL));
        const float Q0 = SUZ2 - SUZ3;
        const float Q1 = K1 * SUZ3;
        SUZ = oneK1 * SUZ3;

        const float SLZ1 = fmaxf(SLZ - cap, NEARZERO_F) + PERC;
        const float Q2 = K2 * SLZ1;
        SLZ = oneK2 * SLZ1;
        CSLZ  = C * SLZ;            // for next step's capillary (off-path)
        CSLZF = CSLZ * invFC;

        op[(size_t)t * G_CELLS] = (Q0 + Q1) + Q2;
    };

    int t = 0;
    // Main: 145 PF-blocks (725 steps) with branchless, always-valid prefetch.
    for (int blk = 0; blk < (T_STEPS / PF) - 1; ++blk) {
#pragma unroll
        for (int i = 0; i < PF; ++i) {
            const float Pt = pP[i], Tt = pT[i], Et = pE[i];
            const float* xp = xphy + ((size_t)(t + PF) * G_CELLS + (size_t)g) * 3;
            pP[i] = xp[0]; pT[i] = xp[1]; pE[i] = xp[2];
            step(Pt, Tt, Et, t);
            ++t;
        }
    }
    // Epilogue: last PF steps, no prefetch.
#pragma unroll
    for (int i = 0; i < PF; ++i) {
        step(pP[i], pT[i], pE[i], t);
        ++t;
    }
}

extern "C" void kernel_launch(void* const* d_in, const int* in_sizes, int n_in,
                              void* d_out, int out_size) {
    const float* xphy   = (const float*)d_in[0];   // 730*8000*3
    const float* params = (const float*)d_in[1];   // 730*8000*14
    float* out = (float*)d_out;                    // 730*8000

    const int threads = 64;
    const int blocks  = (G_CELLS + threads - 1) / threads;  // 125
    hbv_kernel<<<blocks, threads>>>(xphy, params, out);
}

// round 3
// speedup vs baseline: 1.2687x; 1.1602x over previous
#include <cuda_runtime.h>
#include <cstddef>

#define G_CELLS 8000
#define T_STEPS 730
#define PF 5            // 730 = 5 * 146, exact
#define NEARZERO_F 1e-5f

__device__ __forceinline__ float ex2f_(float x) {
    float r; asm("ex2.approx.f32 %0, %1;" : "=f"(r) : "f"(x)); return r;
}
__device__ __forceinline__ float lg2f_(float x) {
    float r; asm("lg2.approx.f32 %0, %1;" : "=f"(r) : "f"(x)); return r;
}

__global__ __launch_bounds__(64) void hbv_kernel(
    const float* __restrict__ xphy,    // [730, 8000, 3] (P, T, PET)
    const float* __restrict__ params,  // [730, 8000, 14]
    float* __restrict__ out)           // [730, 8000]
{
    const int g = blockIdx.x * blockDim.x + threadIdx.x;
    if (g >= G_CELLS) return;

    // BETA, FC, K0, K1, K2, LP, PERCmax, UZL, TT, CFMAX, CFR, CWH, BETAET, C
    const float lo[14] = {1.0f, 50.0f, 0.05f, 0.01f, 0.001f, 0.2f, 0.0f,
                          0.0f, -2.5f, 0.5f, 0.0f, 0.0f, 0.3f, 0.0f};
    const float hi[14] = {6.0f, 1000.0f, 0.9f, 0.5f, 0.2f, 1.0f, 10.0f,
                          100.0f, 2.5f, 10.0f, 0.1f, 0.2f, 5.0f, 1.0f};

    const float* pr = params + ((size_t)(T_STEPS - 1) * G_CELLS + (size_t)g) * 14;
    float phy[14];
#pragma unroll
    for (int i = 0; i < 14; i++) {
        const float s = 1.0f / (1.0f + __expf(-pr[i]));
        phy[i] = fmaf(s, hi[i] - lo[i], lo[i]);
    }
    const float BETA = phy[0],  FC = phy[1],     K0 = phy[2],  K1 = phy[3];
    const float K2 = phy[4],    LP = phy[5],     PERCmax = phy[6];
    const float UZL = phy[7],   TT = phy[8],     CFMAX = phy[9];
    const float CFR = phy[10],  CWH = phy[11],   BETAET = phy[12], C = phy[13];

    const float invFC   = 1.0f / FC;
    const float invLPFC = 1.0f / (LP * FC);
    const float CFRCF   = CFR * CFMAX;          // refreeze factor
    // pow folds: (x*s)^b = ex2( b*lg2(x) + b*lg2(s) )
    const float clgA  = BETA   * lg2f_(invFC);
    const float clgB  = BETAET * lg2f_(invLPFC);
    const float sFCc  = BETAET * lg2f_(1.0f / LP);  // log-domain cap: SM2<=FC
    const float oneK0 = 1.0f - K0;
    const float K0UZL = K0 * UZL;
    const float oneK1 = 1.0f - K1;

    float SP = 0.001f, MW = 0.001f, SM = 0.001f, SUZ = 0.001f, SLZ = 0.001f;
    // capillary constants carried from previous step's SLZ (off-path)
    float CSLZ = C * SLZ;
    float omcf = 1.0f - CSLZ * invFC;           // 1 - C*SLZ/FC

    // Register ring buffer, prefetch depth PF.
    float pP[PF], pT[PF], pE[PF];
#pragma unroll
    for (int i = 0; i < PF; i++) {
        const float* xp = xphy + ((size_t)i * G_CELLS + (size_t)g) * 3;
        pP[i] = xp[0]; pT[i] = xp[1]; pE[i] = xp[2];
    }

    const float* xnext = xphy + (size_t)PF * G_CELLS * 3 + (size_t)g * 3;
    float* op = out + g;

    auto step = [&](float Pt, float Tt, float PETt) {
        // --- snow routine: melt/refreeze unified as signed transfer ---
        const bool  rain = (Tt >= TT);
        const float dT   = Tt - TT;
        const float cfac = rain ? CFMAX : CFRCF;   // melt vs refreeze rate
        const float w    = cfac * dT;              // >=0 melt, <0 -refreeze
        const float RAIN = rain ? Pt : 0.0f;
        const float SNOW = rain ? 0.0f : Pt;
        const float SP1  = SP + SNOW;
        const float transfer = fminf(fmaxf(w, -MW), SP1);
        const float SPd  = SP1 - transfer;         // SP after melt/refreeze
        const float MW2  = MW + transfer;
        const float v    = fmaf(-CWH, SPd, MW2);   // MW2 - CWH*SP
        const float tosoil = fmaxf(v, 0.0f);
        SP = SPd;
        MW = MW2 - tosoil;
        const float inflow = RAIN + tosoil;
        const float u  = SM + RAIN;
        const float t1 = fmaxf(u + v, u);          // SM + inflow

        // --- SM critical cycle ---
        const float lg2SM = lg2f_(SM);
        const float e1  = ex2f_(fmaf(BETA, lg2SM, clgA));      // (SM/FC)^BETA
        const float mid = fmaf(-inflow, e1, t1);
        const float SM1 = fmaxf(mid, SM);          // recharge clip (e1>=1 case)
        const float SM2 = fminf(SM1, FC);          // off-path value
        const float s   = fminf(fmaf(BETAET, lg2f_(SM1), clgB), sFCc); // SM<=FC clamp in log dom
        const float e2  = ex2f_(s);                // (SM2/(LP*FC))^BETAET
        const float floor3 = fmaxf(SM2 - PETt, NEARZERO_F);    // off-path
        const float SM3 = fmaxf(fmaf(-PETt, e2, SM2), floor3); // evap (ef<=1 via floor)
        // capillary folded: SM' = SM3 + clamp(CSLZ - CSLZF*SM3, 0, SLZ)
        const float a = fmaf(omcf, SM3, CSLZ);
        const float c = SM3 + SLZ;
        const float SMn = fmaxf(fminf(a, c), SM3);
        const float cap = SMn - SM3;               // off-path
        SM = SMn;

        // --- response routine (off-path) ---
        const float SUZ1 = SUZ + (t1 - SM2);       // + recharge + excess
        const float PERC = fminf(SUZ1, PERCmax);
        const float SUZ2 = fmaxf(SUZ1 - PERCmax, 0.0f);
        const float SUZ3 = fminf(SUZ2, fmaf(oneK0, SUZ2, K0UZL));
        SUZ = oneK1 * SUZ3;
        const float Q01 = SUZ2 - SUZ;              // Q0 + Q1

        const float SLZ1 = fmaxf(SLZ - cap, NEARZERO_F) + PERC;
        const float Q2 = K2 * SLZ1;
        SLZ = SLZ1 - Q2;
        CSLZ = C * SLZ;                            // next step's capillary
        omcf = fmaf(-CSLZ, invFC, 1.0f);

        *op = Q01 + Q2;
        op += G_CELLS;
    };

    // Main: 145 PF-blocks (725 steps) with branchless, always-valid prefetch.
    for (int blk = 0; blk < (T_STEPS / PF) - 1; ++blk) {
#pragma unroll
        for (int i = 0; i < PF; ++i) {
            const float Pt = pP[i], Tt = pT[i], Et = pE[i];
            pP[i] = xnext[0]; pT[i] = xnext[1]; pE[i] = xnext[2];
            xnext += (size_t)G_CELLS * 3;
            step(Pt, Tt, Et);
        }
    }
    // Epilogue: last PF steps, no prefetch.
#pragma unroll
    for (int i = 0; i < PF; ++i) {
        step(pP[i], pT[i], pE[i]);
    }
}

extern "C" void kernel_launch(void* const* d_in, const int* in_sizes, int n_in,
                              void* d_out, int out_size) {
    const float* xphy   = (const float*)d_in[0];   // 730*8000*3
    const float* params = (const float*)d_in[1];   // 730*8000*14
    float* out = (float*)d_out;                    // 730*8000

    const int threads = 64;
    const int blocks  = (G_CELLS + threads - 1) / threads;  // 125
    hbv_kernel<<<blocks, threads>>>(xphy, params, out);
}

// round 4
// speedup vs baseline: 1.2994x; 1.0242x over previous
#include <cuda_runtime.h>
#include <cstddef>

#define G_CELLS 8000
#define T_STEPS 730
#define PF 5            // 730 = 5 * 146, exact
#define NEARZERO_F 1e-5f

__device__ __forceinline__ float ex2f_(float x) {
    float r; asm("ex2.approx.f32 %0, %1;" : "=f"(r) : "f"(x)); return r;
}
__device__ __forceinline__ float lg2f_(float x) {
    float r; asm("lg2.approx.f32 %0, %1;" : "=f"(r) : "f"(x)); return r;
}

__global__ __launch_bounds__(64, 1) void hbv_kernel(
    const float* __restrict__ xphy,    // [730, 8000, 3] (P, T, PET)
    const float* __restrict__ params,  // [730, 8000, 14]
    float* __restrict__ out)           // [730, 8000]
{
    const int g = blockIdx.x * blockDim.x + threadIdx.x;
    if (g >= G_CELLS) return;

    // BETA, FC, K0, K1, K2, LP, PERCmax, UZL, TT, CFMAX, CFR, CWH, BETAET, C
    const float lo[14] = {1.0f, 50.0f, 0.05f, 0.01f, 0.001f, 0.2f, 0.0f,
                          0.0f, -2.5f, 0.5f, 0.0f, 0.0f, 0.3f, 0.0f};
    const float hi[14] = {6.0f, 1000.0f, 0.9f, 0.5f, 0.2f, 1.0f, 10.0f,
                          100.0f, 2.5f, 10.0f, 0.1f, 0.2f, 5.0f, 1.0f};

    const float* pr = params + ((size_t)(T_STEPS - 1) * G_CELLS + (size_t)g) * 14;
    float phy[14];
#pragma unroll
    for (int i = 0; i < 14; i++) {
        const float s = 1.0f / (1.0f + __expf(-pr[i]));
        phy[i] = fmaf(s, hi[i] - lo[i], lo[i]);
    }
    const float BETA = phy[0],  FC = phy[1],     K0 = phy[2],  K1 = phy[3];
    const float K2 = phy[4],    LP = phy[5],     PERCmax = phy[6];
    const float UZL = phy[7],   TT = phy[8],     CFMAX = phy[9];
    const float CFR = phy[10],  CWH = phy[11],   BETAET = phy[12], C = phy[13];

    const float invFC   = 1.0f / FC;
    const float invLPFC = 1.0f / (LP * FC);
    const float CFRCF   = CFR * CFMAX;
    // pow folds: (x*s)^b = ex2( b*lg2(x) + b*lg2(s) )
    const float clgA  = BETA   * lg2f_(invFC);
    const float clgB  = BETAET * lg2f_(invLPFC);
    const float sFCc  = BETAET * lg2f_(1.0f / LP);  // log-domain cap: SM<=FC
    const float oneK0 = 1.0f - K0;
    const float K0UZL = K0 * UZL;
    const float oneK1 = 1.0f - K1;

    float SP = 0.001f, MW = 0.001f, SM = 0.001f, SUZ = 0.001f, SLZ = 0.001f;
    // capillary constants carried from previous step's SLZ (off-path)
    float CSLZ = C * SLZ;
    float omcf = 1.0f - CSLZ * invFC;           // 1 - C*SLZ/FC

    // Ring buffers hold INPUT-DERIVED quantities, computed at prefetch time
    // (they depend only on inputs + per-cell constants, not on state).
    float rRAIN[PF], rSNOW[PF], rW[PF], rPET[PF];

    const float* xp = xphy + (size_t)g * 3;
#pragma unroll
    for (int i = 0; i < PF; i++) {
        const float P = xp[0], Tm = xp[1], PE = xp[2];
        xp += G_CELLS * 3;
        const bool rain = (Tm >= TT);
        rRAIN[i] = rain ? P : 0.0f;
        rSNOW[i] = rain ? 0.0f : P;
        rW[i]    = (rain ? CFMAX : CFRCF) * (Tm - TT);  // melt (+) / -refreeze (-)
        rPET[i]  = PE;
    }

    float* op = out + g;

    auto step = [&](float RAIN, float SNOW, float w, float PETt) {
        // --- snow routine: pure state updates (input math precomputed) ---
        const float SP1 = SP + SNOW;
        const float transfer = fminf(fmaxf(w, -MW), SP1);
        const float SPd = SP1 - transfer;
        const float MW2 = MW + transfer;
        const float v   = fmaf(-CWH, SPd, MW2);    // MW2 - CWH*SP
        const float tosoil = fmaxf(v, 0.0f);
        SP = SPd;
        MW = MW2 - tosoil;
        const float inflow = RAIN + tosoil;
        const float u  = SM + RAIN;
        const float t1 = fmaxf(u + v, u);          // SM + inflow

        // --- SM critical cycle ---
        // e1 = min((SM/FC)^BETA, 1): clamp in log domain (exact, ex2 monotone,
        // ex2(0)=1). Guarantees e1<=1 => SM1 >= SM, so no post-clip needed.
        const float s1 = fminf(fmaf(BETA, lg2f_(SM), clgA), 0.0f);
        const float e1 = ex2f_(s1);
        const float SM1 = fmaf(-inflow, e1, t1);
        const float SM2 = fminf(SM1, FC);          // off the lg2 path
        const float s2 = fminf(fmaf(BETAET, lg2f_(SM1), clgB), sFCc);
        const float e2 = ex2f_(s2);                // (SM2/(LP*FC))^BETAET
        const float floor3 = fmaxf(SM2 - PETt, NEARZERO_F);   // off-path
        const float SM3 = fmaxf(fmaf(-PETt, e2, SM2), floor3);
        // capillary folded: SM' = SM3 + clamp(CSLZ - (CSLZ/FC)*SM3, 0, SLZ)
        const float a = fmaf(omcf, SM3, CSLZ);
        const float SMn = fmaxf(fminf(a, SM3 + SLZ), SM3);
        const float cap = SMn - SM3;               // off-path
        SM = SMn;

        // --- response routine (off-path) ---
        const float SUZ1 = SUZ + (t1 - SM2);       // + recharge + excess
        const float PERC = fminf(SUZ1, PERCmax);
        const float SUZ2 = fmaxf(SUZ1 - PERCmax, 0.0f);
        const float SUZ3 = fminf(SUZ2, fmaf(oneK0, SUZ2, K0UZL));
        SUZ = oneK1 * SUZ3;
        const float Q01 = SUZ2 - SUZ;              // Q0 + Q1

        const float SLZ1 = fmaxf(SLZ - cap, NEARZERO_F) + PERC;
        const float Q2 = K2 * SLZ1;
        SLZ = SLZ1 - Q2;
        CSLZ = C * SLZ;                            // next step's capillary
        omcf = fmaf(-CSLZ, invFC, 1.0f);

        *op = Q01 + Q2;
        op += G_CELLS;
    };

    // Main: 145 PF-blocks (725 steps), branchless always-valid prefetch.
    for (int blk = 0; blk < (T_STEPS / PF) - 1; ++blk) {
#pragma unroll
        for (int i = 0; i < PF; ++i) {
            const float RAIN = rRAIN[i], SNOW = rSNOW[i];
            const float w = rW[i], PE = rPET[i];
            // prefetch + input-only precompute for step t+PF
            {
                const float P = xp[0], Tm = xp[1], PEn = xp[2];
                xp += G_CELLS * 3;
                const bool rain = (Tm >= TT);
                rRAIN[i] = rain ? P : 0.0f;
                rSNOW[i] = rain ? 0.0f : P;
                rW[i]    = (rain ? CFMAX : CFRCF) * (Tm - TT);
                rPET[i]  = PEn;
            }
            step(RAIN, SNOW, w, PE);
        }
    }
    // Epilogue: last PF steps, no prefetch.
#pragma unroll
    for (int i = 0; i < PF; ++i) {
        step(rRAIN[i], rSNOW[i], rW[i], rPET[i]);
    }
}

extern "C" void kernel_launch(void* const* d_in, const int* in_sizes, int n_in,
                              void* d_out, int out_size) {
    const float* xphy   = (const float*)d_in[0];   // 730*8000*3
    const float* params = (const float*)d_in[1];   // 730*8000*14
    float* out = (float*)d_out;                    // 730*8000

    const int threads = 64;
    const int blocks  = (G_CELLS + threads - 1) / threads;  // 125
    hbv_kernel<<<blocks, threads>>>(xphy, params, out);
}